// round 15
// baseline (speedup 1.0000x reference)
#include <cuda_runtime.h>
#include <cuda_fp16.h>
#include <math.h>
#include <float.h>
#include <stdint.h>

#define BB 4
#define NN 4096
#define LL 256
#define KSEL 20
#define EPSF 1e-6f

// ---------------- scratch (static device globals; no allocation) ----------------
__device__ uint32_t g_hi[(size_t)BB * NN * 128];
__device__ uint32_t g_lo[(size_t)BB * NN * 128];
__device__ float g_sim[(size_t)BB * NN * NN];            // masked cols = -FLT_MAX
__device__ uint32_t g_maskbits[BB * (NN / 32)];
__device__ int g_cnt[BB][32];                            // rowblock completion counters

// ---------------- kernel 0: mask -> bitmask + counter reset ----------------
__global__ void kmask(const int* __restrict__ mask) {
    int b = blockIdx.x;
    int t = threadIdx.x;
    uint32_t w = 0;
#pragma unroll
    for (int q = 0; q < 32; q++)
        w |= (mask[b * NN + t * 32 + q] != 0 ? 1u : 0u) << q;
    g_maskbits[b * (NN / 32) + t] = w;
    if (t < 32) g_cnt[b][t] = 0;
}

// ---------------- kernel 1: per-row normalization + fp16 hi/lo split ------------
__global__ __launch_bounds__(128) void knorm(const float* __restrict__ hist,
                                             const int* __restrict__ mask) {
    int row = blockIdx.x * 4 + (threadIdx.x >> 5);
    if (row >= BB * NN) return;
    int lane = threadIdx.x & 31;
    const float* x = hist + (size_t)row * LL;

    float v[8];
#pragma unroll
    for (int i = 0; i < 2; i++) {
        float4 t = ((const float4*)x)[lane + i * 32];
        v[i * 4 + 0] = t.x; v[i * 4 + 1] = t.y; v[i * 4 + 2] = t.z; v[i * 4 + 3] = t.w;
    }
    float s = 0.f;
#pragma unroll
    for (int i = 0; i < 8; i++) s += v[i];
#pragma unroll
    for (int off = 16; off; off >>= 1) s += __shfl_xor_sync(0xffffffffu, s, off);
    float mean = s * (1.f / LL);

    float ss = 0.f;
#pragma unroll
    for (int i = 0; i < 8; i++) { float d = v[i] - mean; ss += d * d; }
#pragma unroll
    for (int off = 16; off; off >>= 1) ss += __shfl_xor_sync(0xffffffffu, ss, off);

    float denom = fmaxf(sqrtf(ss * (1.f / LL)), EPSF);
    float scale = (mask[row] != 0 ? 1.f : 0.f) / denom;

    uint32_t* ph = g_hi + (size_t)row * 128;
    uint32_t* pl = g_lo + (size_t)row * 128;
#pragma unroll
    for (int i = 0; i < 2; i++) {
        int q0 = 2 * (lane + 32 * i);
#pragma unroll
        for (int pp = 0; pp < 2; pp++) {
            int q = q0 + pp;
            float y0 = (v[i * 4 + 2 * pp + 0] - mean) * scale;
            float y1 = (v[i * 4 + 2 * pp + 1] - mean) * scale;
            __half h0 = __float2half_rn(y0);
            __half h1 = __float2half_rn(y1);
            __half l0 = __float2half_rn(y0 - __half2float(h0));
            __half l1 = __float2half_rn(y1 - __half2float(h1));
            int c = q >> 4;
            int qq = q & 15;
            int ks = qq >> 3;
            int hs = (qq >> 2) & 1;
            int tg = qq & 3;
            int upos = c * 16 + 2 * (ks * 4 + tg) + hs;
            __half2 hh = __halves2half2(h0, h1);
            __half2 ll = __halves2half2(l0, l1);
            ph[upos] = *(uint32_t*)&hh;
            pl[upos] = *(uint32_t*)&ll;
        }
    }
}

// ---------------- kernel 2: FUSED gemm + per-row topk with tile-ready spin ------
#define BM 128
#define BN 128
#define NKB 8
#define NTILE (NN / BM)                  // 32
#define NUPPER (NTILE * (NTILE + 1) / 2) // 528
#define NGEMM (NUPPER * BB)              // 2112
#define TSTRIDE 132
#define TILE_B 8192
#define STAGE_B 32768
#define SMEM_TOT (3 * STAGE_B)           // 98304

__device__ __forceinline__ void mma_f16(float* d,
                                        uint32_t a0, uint32_t a1, uint32_t a2, uint32_t a3,
                                        uint32_t b0, uint32_t b1) {
    asm volatile(
        "mma.sync.aligned.m16n8k16.row.col.f32.f16.f16.f32 "
        "{%0,%1,%2,%3}, {%4,%5,%6,%7}, {%8,%9}, {%0,%1,%2,%3};"
        : "+f"(d[0]), "+f"(d[1]), "+f"(d[2]), "+f"(d[3])
        : "r"(a0), "r"(a1), "r"(a2), "r"(a3), "r"(b0), "r"(b1));
}

#define CPA16(dst32, src) \
    asm volatile("cp.async.cg.shared.global [%0], [%1], 16;\n" :: "r"(dst32), "l"(src))

__global__ __launch_bounds__(256, 2) void kfused(float* __restrict__ out) {
    extern __shared__ char smem[];
    int tid = threadIdx.x;

    // =================== TOPK ROLE ===================
    if (blockIdx.x >= NGEMM) {
        int r = blockIdx.x - NGEMM;
        int b = r >> 12;                 // 4096 rows per batch
        int row = r & (NN - 1);
        int rb = row >> 7;               // rowblock 0..31

        // wait for all 32 tiles covering this rowblock
        if (tid == 0) {
            while (atomicAdd(&g_cnt[b][rb], 0) < 32) __nanosleep(128);
            __threadfence();
        }
        __syncthreads();

        const float* simrow = g_sim + ((size_t)b * NN + row) * NN;
        float* orow = out + ((size_t)b * NN + row) * NN;

        float* sv = (float*)smem;                    // 4096 floats
        float* cv = sv + NN;                         // 256 chunk heads
        float* sel_v = cv + 256;                     // 20
        int*   sel_i = (int*)(sel_v + KSEL);         // 20
        float* fsc = (float*)(sel_i + KSEL);

        int lane = tid & 31;

        // load + value-only chunk max (chunk = 16 elems: {4t + 1024j + e})
        {
            float m = -INFINITY;
#pragma unroll
            for (int j = 0; j < 4; j++) {
                int i = tid * 4 + 1024 * j;
                float4 v = *(const float4*)(simrow + i);
                *(float4*)(sv + i) = v;
                m = fmaxf(m, fmaxf(fmaxf(v.x, v.y), fmaxf(v.z, v.w)));
            }
            cv[tid] = m;
        }
        __syncthreads();

        if (tid < 32) {
            for (int it = 0; it < KSEL; it++) {
                float bv = cv[lane]; int bc = lane;
#pragma unroll
                for (int t2 = 1; t2 < 8; t2++) {
                    float v = cv[lane + 32 * t2];
                    if (v > bv) { bv = v; bc = lane + 32 * t2; }
                }
#pragma unroll
                for (int off = 16; off; off >>= 1) {
                    float ov = __shfl_xor_sync(0xffffffffu, bv, off);
                    int   oc = __shfl_xor_sync(0xffffffffu, bc, off);
                    if (ov > bv || (ov == bv && oc < bc)) { bv = ov; bc = oc; }
                }
                // rescan chunk bc (16 elems; lanes 16-31 duplicate 0-15)
                int l2 = lane & 15;
                int idx = 4 * bc + 1024 * (l2 >> 2) + (l2 & 3);
                float nv = sv[idx]; int ni = idx;
#pragma unroll
                for (int off = 16; off; off >>= 1) {
                    float ov = __shfl_xor_sync(0xffffffffu, nv, off);
                    int   oi = __shfl_xor_sync(0xffffffffu, ni, off);
                    if (ov > nv || (ov == nv && oi < ni)) { nv = ov; ni = oi; }
                }
                if (lane == 0) {
                    sel_v[it] = nv;
                    sel_i[it] = ni;
                    sv[ni] = -INFINITY;
                }
                __syncwarp();
                float hv = sv[idx];
#pragma unroll
                for (int off = 16; off; off >>= 1)
                    hv = fmaxf(hv, __shfl_xor_sync(0xffffffffu, hv, off));
                if (lane == 0) cv[bc] = hv;
                __syncwarp();
            }
            if (lane == 0) {
                float S = 0.f;
#pragma unroll
                for (int t2 = 0; t2 < KSEL; t2++) {
                    float v = sel_v[t2];
                    if (v < 0.f) v = 0.f;            // masked (-FLT_MAX) / negative -> 0
                    if (sel_i[t2] == row) v = 0.f;   // diagonal
                    sel_v[t2] = v;
                    S += v;
                }
                float r1 = 1.f / fmaxf(S, EPSF);
                float S1 = S * r1;
                float r2 = 1.f / fmaxf(S1, EPSF);
                *fsc = r1 * r2;
            }
        }
        __syncthreads();

        // write full zero row, then scatter 20 normalized values
        float4 z = {0.f, 0.f, 0.f, 0.f};
#pragma unroll
        for (int j = 0; j < 4; j++)
            *(float4*)(orow + tid * 4 + 1024 * j) = z;
        __syncthreads();
        if (tid < KSEL) orow[sel_i[tid]] = sel_v[tid] * (*fsc);
        return;
    }

    // =================== GEMM ROLE ===================
    int xg = blockIdx.x;
    int b = xg / NUPPER;
    int t = xg % NUPPER;
    int ti = 0;
    while (t >= NTILE - ti) { t -= NTILE - ti; ti++; }
    int tj = ti + t;

    int tileM = ti * BM;
    int tileN = tj * BN;
    const uint32_t* __restrict__ Ph = g_hi + (size_t)b * NN * 128;
    const uint32_t* __restrict__ Pl = g_lo + (size_t)b * NN * 128;
    float* __restrict__ C = g_sim + (size_t)b * NN * NN;

    int wid = tid >> 5;
    int lane = tid & 31;
    int g = lane >> 2;
    int tg = lane & 3;
    int pg = (g >> 1) & 1;
    int m0w = (wid & 1) * 64;
    int n0w = (wid >> 1) * 32;

    int lr = tid >> 1;
    int lh = tid & 1;
    int rot = 2 * ((lr >> 1) & 1);
    uint32_t sbase = (uint32_t)__cvta_generic_to_shared(smem);

    float acc[4][4][4];
#pragma unroll
    for (int i = 0; i < 4; i++)
#pragma unroll
        for (int j = 0; j < 4; j++)
#pragma unroll
            for (int q = 0; q < 4; q++) acc[i][j][q] = 0.f;

    // prologue: stages 0,1
#pragma unroll
    for (int ps = 0; ps < 2; ps++) {
        const uint32_t* srcs[4] = {
            Ph + (size_t)(tileM + lr) * 128 + ps * 16,
            Pl + (size_t)(tileM + lr) * 128 + ps * 16,
            Ph + (size_t)(tileN + lr) * 128 + ps * 16,
            Pl + (size_t)(tileN + lr) * 128 + ps * 16 };
        uint32_t st = sbase + ps * STAGE_B;
#pragma unroll
        for (int tt = 0; tt < 4; tt++) {
            uint32_t dbase = st + tt * TILE_B + lr * 64;
#pragma unroll
            for (int gg2 = 0; gg2 < 2; gg2++) {
                int gg = 2 * lh + gg2;
                CPA16(dbase + (((gg + rot) & 3) * 16), srcs[tt] + gg * 4);
            }
        }
        asm volatile("cp.async.commit_group;");
    }

    for (int kb = 0; kb < NKB; kb++) {
        if (kb < NKB - 1) asm volatile("cp.async.wait_group 1;");
        else              asm volatile("cp.async.wait_group 0;");
        __syncthreads();

        if (kb + 2 < NKB) {
            int c = kb + 2;
            const uint32_t* srcs[4] = {
                Ph + (size_t)(tileM + lr) * 128 + c * 16,
                Pl + (size_t)(tileM + lr) * 128 + c * 16,
                Ph + (size_t)(tileN + lr) * 128 + c * 16,
                Pl + (size_t)(tileN + lr) * 128 + c * 16 };
            uint32_t st = sbase + (c % 3) * STAGE_B;
#pragma unroll
            for (int tt = 0; tt < 4; tt++) {
                uint32_t dbase = st + tt * TILE_B + lr * 64;
#pragma unroll
                for (int gg2 = 0; gg2 < 2; gg2++) {
                    int gg = 2 * lh + gg2;
                    CPA16(dbase + (((gg + rot) & 3) * 16), srcs[tt] + gg * 4);
                }
            }
            asm volatile("cp.async.commit_group;");
        }

        const char* sbuf = smem + (kb % 3) * STAGE_B;
#pragma unroll
        for (int ks = 0; ks < 2; ks++) {
            int dq = ((ks << 2) + tg + (pg << 2)) & 7;
            uint2 AH0[4], AH1[4], AL0[4], AL1[4];
#pragma unroll
            for (int i = 0; i < 4; i++) {
                const char* a0p = sbuf + (m0w + 16 * i + g) * 64 + dq * 8;
                AH0[i] = *(const uint2*)(a0p);
                AH1[i] = *(const uint2*)(a0p + 8 * 64);
                AL0[i] = *(const uint2*)(a0p + TILE_B);
                AL1[i] = *(const uint2*)(a0p + TILE_B + 8 * 64);
            }
#pragma unroll
            for (int j = 0; j < 4; j++) {
                const char* bp = sbuf + 2 * TILE_B + (n0w + 8 * j + g) * 64 + dq * 8;
                uint2 BH = *(const uint2*)(bp);
                uint2 BL = *(const uint2*)(bp + TILE_B);
#pragma unroll
                for (int i = 0; i < 4; i++) {
                    mma_f16(acc[i][j], AH0[i].x, AH1[i].x, AH0[i].y, AH1[i].y, BH.x, BH.y);
                    mma_f16(acc[i][j], AH0[i].x, AH1[i].x, AH0[i].y, AH1[i].y, BL.x, BL.y);
                    mma_f16(acc[i][j], AL0[i].x, AL1[i].x, AL0[i].y, AL1[i].y, BH.x, BH.y);
                }
            }
        }
    }

    // epilogue: relu/scale/diag + column-mask fold -> sim
    const float inv_l = 1.f / LL;
    const uint32_t* mb = g_maskbits + b * (NN / 32);
    uint4 mwNv = *(const uint4*)(mb + (tileN >> 5));
    uint4 mwMv = *(const uint4*)(mb + (tileM >> 5));
    uint32_t mwN[4] = {mwNv.x, mwNv.y, mwNv.z, mwNv.w};
    uint32_t mwM[4] = {mwMv.x, mwMv.y, mwMv.z, mwMv.w};

#pragma unroll
    for (int i = 0; i < 4; i++) {
        int gm0 = tileM + m0w + i * 16 + g;
        int gm1 = gm0 + 8;
#pragma unroll
        for (int j = 0; j < 4; j++) {
            int nl = n0w + j * 8 + 2 * tg;
            int gn = tileN + nl;
            float v0 = fmaxf(acc[i][j][0] * inv_l, 0.f);
            float v1 = fmaxf(acc[i][j][1] * inv_l, 0.f);
            float v2 = fmaxf(acc[i][j][2] * inv_l, 0.f);
            float v3 = fmaxf(acc[i][j][3] * inv_l, 0.f);
            if (gm0 == gn)     v0 = 0.f;
            if (gm0 == gn + 1) v1 = 0.f;
            if (gm1 == gn)     v2 = 0.f;
            if (gm1 == gn + 1) v3 = 0.f;
            acc[i][j][0] = v0; acc[i][j][1] = v1;
            acc[i][j][2] = v2; acc[i][j][3] = v3;
            uint32_t q0 = (mwN[nl >> 5] >> (nl & 31)) & 1u;
            uint32_t q1 = (mwN[nl >> 5] >> ((nl + 1) & 31)) & 1u;
            float2 r0, r1;
            r0.x = q0 ? v0 : -FLT_MAX; r0.y = q1 ? v1 : -FLT_MAX;
            r1.x = q0 ? v2 : -FLT_MAX; r1.y = q1 ? v3 : -FLT_MAX;
            *(float2*)(C + (size_t)gm0 * NN + gn) = r0;
            *(float2*)(C + (size_t)gm1 * NN + gn) = r1;
        }
    }

    // mirror tile (column mask = M-side)
    if (ti != tj) {
        float* stg = (float*)smem;
        __syncthreads();
#pragma unroll
        for (int i = 0; i < 4; i++) {
            int ml0 = m0w + i * 16 + g;
            int ml1 = ml0 + 8;
            uint32_t q0 = (mwM[ml0 >> 5] >> (ml0 & 31)) & 1u;
            uint32_t q1 = (mwM[ml1 >> 5] >> (ml1 & 31)) & 1u;
#pragma unroll
            for (int j = 0; j < 4; j++) {
                int nl = n0w + j * 8 + 2 * tg;
                stg[(nl)     * TSTRIDE + ml0] = q0 ? acc[i][j][0] : -FLT_MAX;
                stg[(nl + 1) * TSTRIDE + ml0] = q0 ? acc[i][j][1] : -FLT_MAX;
                stg[(nl)     * TSTRIDE + ml1] = q1 ? acc[i][j][2] : -FLT_MAX;
                stg[(nl + 1) * TSTRIDE + ml1] = q1 ? acc[i][j][3] : -FLT_MAX;
            }
        }
        __syncthreads();
#pragma unroll
        for (int it = 0; it < 16; it++) {
            int idx = it * 256 + tid;
            int rr = idx >> 5;
            int c4 = idx & 31;
            float4 v = *(const float4*)&stg[rr * TSTRIDE + c4 * 4];
            *(float4*)(C + (size_t)(tileN + rr) * NN + tileM + c4 * 4) = v;
        }
    }

    // publish tile completion (release: fence all threads' stores, then count)
    __threadfence();
    __syncthreads();
    if (tid == 0) {
        atomicAdd(&g_cnt[b][ti], 1);
        if (ti != tj) atomicAdd(&g_cnt[b][tj], 1);
    }
}

// ---------------- launch ----------------
extern "C" void kernel_launch(void* const* d_in, const int* in_sizes, int n_in,
                              void* d_out, int out_size) {
    const float* hist = (const float*)d_in[0];
    const int* mask = (const int*)d_in[1];
    float* out = (float*)d_out;

    static int smem_set = 0;
    if (!smem_set) {
        cudaFuncSetAttribute(kfused, cudaFuncAttributeMaxDynamicSharedMemorySize, SMEM_TOT);
        smem_set = 1;
    }

    kmask<<<BB, NN / 32>>>(mask);
    knorm<<<(BB * NN) / 4, 128>>>(hist, mask);

    kfused<<<NGEMM + BB * NN, 256, SMEM_TOT>>>(out);
}

// round 16
// speedup vs baseline: 2.2746x; 2.2746x over previous
#include <cuda_runtime.h>
#include <cuda_fp16.h>
#include <math.h>
#include <float.h>
#include <stdint.h>

#define BB 4
#define NN 4096
#define LL 256
#define KSEL 20
#define EPSF 1e-6f

// ---------------- scratch (static device globals; no allocation) ----------------
__device__ uint32_t g_hi[(size_t)BB * NN * 128];
__device__ uint32_t g_lo[(size_t)BB * NN * 128];
__device__ float g_sim[(size_t)BB * NN * NN];            // masked cols = -FLT_MAX
__device__ uint32_t g_maskbits[BB * (NN / 32)];

// ---------------- kernel 0: mask -> bitmask ----------------
__global__ void kmask(const int* __restrict__ mask) {
    int b = blockIdx.x;
    int t = threadIdx.x;
    uint32_t w = 0;
#pragma unroll
    for (int q = 0; q < 32; q++)
        w |= (mask[b * NN + t * 32 + q] != 0 ? 1u : 0u) << q;
    g_maskbits[b * (NN / 32) + t] = w;
}

// ---------------- kernel 1: per-row normalization + fp16 hi/lo split ------------
__global__ __launch_bounds__(128) void knorm(const float* __restrict__ hist,
                                             const int* __restrict__ mask) {
    int row = blockIdx.x * 4 + (threadIdx.x >> 5);
    if (row >= BB * NN) return;
    int lane = threadIdx.x & 31;
    const float* x = hist + (size_t)row * LL;

    float v[8];
#pragma unroll
    for (int i = 0; i < 2; i++) {
        float4 t = ((const float4*)x)[lane + i * 32];
        v[i * 4 + 0] = t.x; v[i * 4 + 1] = t.y; v[i * 4 + 2] = t.z; v[i * 4 + 3] = t.w;
    }
    float s = 0.f;
#pragma unroll
    for (int i = 0; i < 8; i++) s += v[i];
#pragma unroll
    for (int off = 16; off; off >>= 1) s += __shfl_xor_sync(0xffffffffu, s, off);
    float mean = s * (1.f / LL);

    float ss = 0.f;
#pragma unroll
    for (int i = 0; i < 8; i++) { float d = v[i] - mean; ss += d * d; }
#pragma unroll
    for (int off = 16; off; off >>= 1) ss += __shfl_xor_sync(0xffffffffu, ss, off);

    float denom = fmaxf(sqrtf(ss * (1.f / LL)), EPSF);
    float scale = (mask[row] != 0 ? 1.f : 0.f) / denom;

    uint32_t* ph = g_hi + (size_t)row * 128;
    uint32_t* pl = g_lo + (size_t)row * 128;
#pragma unroll
    for (int i = 0; i < 2; i++) {
        int q0 = 2 * (lane + 32 * i);
#pragma unroll
        for (int pp = 0; pp < 2; pp++) {
            int q = q0 + pp;
            float y0 = (v[i * 4 + 2 * pp + 0] - mean) * scale;
            float y1 = (v[i * 4 + 2 * pp + 1] - mean) * scale;
            __half h0 = __float2half_rn(y0);
            __half h1 = __float2half_rn(y1);
            __half l0 = __float2half_rn(y0 - __half2float(h0));
            __half l1 = __float2half_rn(y1 - __half2float(h1));
            int c = q >> 4;
            int qq = q & 15;
            int ks = qq >> 3;
            int hs = (qq >> 2) & 1;
            int tg = qq & 3;
            int upos = c * 16 + 2 * (ks * 4 + tg) + hs;
            __half2 hh = __halves2half2(h0, h1);
            __half2 ll = __halves2half2(l0, l1);
            ph[upos] = *(uint32_t*)&hh;
            pl[upos] = *(uint32_t*)&ll;
        }
    }
}

// ---------------- kernel 2: fp16x2 GEMM, 3-stage pipeline + fused zero-fill -----
#define BM 128
#define BN 128
#define NKB 8
#define NTILE (NN / BM)                  // 32
#define NUPPER (NTILE * (NTILE + 1) / 2) // 528
#define ZBLK 128
#define ZSLICE (NN * NN / ZBLK)
#define TSTRIDE 132
#define TILE_B 8192
#define STAGE_B 32768
#define SMEM_TOT (3 * STAGE_B)           // 98304

__device__ __forceinline__ void mma_f16(float* d,
                                        uint32_t a0, uint32_t a1, uint32_t a2, uint32_t a3,
                                        uint32_t b0, uint32_t b1) {
    asm volatile(
        "mma.sync.aligned.m16n8k16.row.col.f32.f16.f16.f32 "
        "{%0,%1,%2,%3}, {%4,%5,%6,%7}, {%8,%9}, {%0,%1,%2,%3};"
        : "+f"(d[0]), "+f"(d[1]), "+f"(d[2]), "+f"(d[3])
        : "r"(a0), "r"(a1), "r"(a2), "r"(a3), "r"(b0), "r"(b1));
}

#define CPA16(dst32, src) \
    asm volatile("cp.async.cg.shared.global [%0], [%1], 16;\n" :: "r"(dst32), "l"(src))

__global__ __launch_bounds__(256, 2) void kgemm(float* __restrict__ outz) {
    extern __shared__ char smem[];

    int t = blockIdx.x;
    int b = blockIdx.z;
    int tid = threadIdx.x;

    // ---- fused zero-fill duty (overlaps with GEMM waves) ----
    if (t >= NUPPER) {
        int zb = t - NUPPER;
        float4* p = (float4*)(outz + (size_t)b * NN * NN + (size_t)zb * ZSLICE) + tid;
        float4 z = {0.f, 0.f, 0.f, 0.f};
#pragma unroll 8
        for (int it = 0; it < ZSLICE / 1024; it++)
            p[it * 256] = z;
        return;
    }

    int ti = 0;
    while (t >= NTILE - ti) { t -= NTILE - ti; ti++; }
    int tj = ti + t;

    int tileM = ti * BM;
    int tileN = tj * BN;
    const uint32_t* __restrict__ Ph = g_hi + (size_t)b * NN * 128;
    const uint32_t* __restrict__ Pl = g_lo + (size_t)b * NN * 128;
    float* __restrict__ C = g_sim + (size_t)b * NN * NN;

    int wid = tid >> 5;
    int lane = tid & 31;
    int g = lane >> 2;
    int tg = lane & 3;
    int pg = (g >> 1) & 1;
    int m0w = (wid & 1) * 64;
    int n0w = (wid >> 1) * 32;

    int lr = tid >> 1;
    int lh = tid & 1;
    int rot = 2 * ((lr >> 1) & 1);
    uint32_t sbase = (uint32_t)__cvta_generic_to_shared(smem);

    float acc[4][4][4];
#pragma unroll
    for (int i = 0; i < 4; i++)
#pragma unroll
        for (int j = 0; j < 4; j++)
#pragma unroll
            for (int q = 0; q < 4; q++) acc[i][j][q] = 0.f;

    // prologue: stages 0,1 (chunks 0,1), one commit group each
#pragma unroll
    for (int ps = 0; ps < 2; ps++) {
        const uint32_t* srcs[4] = {
            Ph + (size_t)(tileM + lr) * 128 + ps * 16,
            Pl + (size_t)(tileM + lr) * 128 + ps * 16,
            Ph + (size_t)(tileN + lr) * 128 + ps * 16,
            Pl + (size_t)(tileN + lr) * 128 + ps * 16 };
        uint32_t st = sbase + ps * STAGE_B;
#pragma unroll
        for (int tt = 0; tt < 4; tt++) {
            uint32_t dbase = st + tt * TILE_B + lr * 64;
#pragma unroll
            for (int gg2 = 0; gg2 < 2; gg2++) {
                int gg = 2 * lh + gg2;
                CPA16(dbase + (((gg + rot) & 3) * 16), srcs[tt] + gg * 4);
            }
        }
        asm volatile("cp.async.commit_group;");
    }

    for (int kb = 0; kb < NKB; kb++) {
        if (kb < NKB - 1) asm volatile("cp.async.wait_group 1;");
        else              asm volatile("cp.async.wait_group 0;");
        __syncthreads();

        if (kb + 2 < NKB) {
            int c = kb + 2;
            const uint32_t* srcs[4] = {
                Ph + (size_t)(tileM + lr) * 128 + c * 16,
                Pl + (size_t)(tileM + lr) * 128 + c * 16,
                Ph + (size_t)(tileN + lr) * 128 + c * 16,
                Pl + (size_t)(tileN + lr) * 128 + c * 16 };
            uint32_t st = sbase + (c % 3) * STAGE_B;
#pragma unroll
            for (int tt = 0; tt < 4; tt++) {
                uint32_t dbase = st + tt * TILE_B + lr * 64;
#pragma unroll
                for (int gg2 = 0; gg2 < 2; gg2++) {
                    int gg = 2 * lh + gg2;
                    CPA16(dbase + (((gg + rot) & 3) * 16), srcs[tt] + gg * 4);
                }
            }
            asm volatile("cp.async.commit_group;");
        }

        const char* sbuf = smem + (kb % 3) * STAGE_B;
#pragma unroll
        for (int ks = 0; ks < 2; ks++) {
            int dq = ((ks << 2) + tg + (pg << 2)) & 7;
            uint2 AH0[4], AH1[4], AL0[4], AL1[4];
#pragma unroll
            for (int i = 0; i < 4; i++) {
                const char* a0p = sbuf + (m0w + 16 * i + g) * 64 + dq * 8;
                AH0[i] = *(const uint2*)(a0p);
                AH1[i] = *(const uint2*)(a0p + 8 * 64);
                AL0[i] = *(const uint2*)(a0p + TILE_B);
                AL1[i] = *(const uint2*)(a0p + TILE_B + 8 * 64);
            }
#pragma unroll
            for (int j = 0; j < 4; j++) {
                const char* bp = sbuf + 2 * TILE_B + (n0w + 8 * j + g) * 64 + dq * 8;
                uint2 BH = *(const uint2*)(bp);
                uint2 BL = *(const uint2*)(bp + TILE_B);
#pragma unroll
                for (int i = 0; i < 4; i++) {
                    mma_f16(acc[i][j], AH0[i].x, AH1[i].x, AH0[i].y, AH1[i].y, BH.x, BH.y);
                    mma_f16(acc[i][j], AH0[i].x, AH1[i].x, AH0[i].y, AH1[i].y, BL.x, BL.y);
                    mma_f16(acc[i][j], AL0[i].x, AL1[i].x, AL0[i].y, AL1[i].y, BH.x, BH.y);
                }
            }
        }
    }

    // ---- epilogue: relu/scale/diag + column-mask fold -> sim ----
    const float inv_l = 1.f / LL;
    const uint32_t* mb = g_maskbits + b * (NN / 32);
    uint4 mwNv = *(const uint4*)(mb + (tileN >> 5));
    uint4 mwMv = *(const uint4*)(mb + (tileM >> 5));
    uint32_t mwN[4] = {mwNv.x, mwNv.y, mwNv.z, mwNv.w};
    uint32_t mwM[4] = {mwMv.x, mwMv.y, mwMv.z, mwMv.w};

#pragma unroll
    for (int i = 0; i < 4; i++) {
        int gm0 = tileM + m0w + i * 16 + g;
        int gm1 = gm0 + 8;
#pragma unroll
        for (int j = 0; j < 4; j++) {
            int nl = n0w + j * 8 + 2 * tg;
            int gn = tileN + nl;
            float v0 = fmaxf(acc[i][j][0] * inv_l, 0.f);
            float v1 = fmaxf(acc[i][j][1] * inv_l, 0.f);
            float v2 = fmaxf(acc[i][j][2] * inv_l, 0.f);
            float v3 = fmaxf(acc[i][j][3] * inv_l, 0.f);
            if (gm0 == gn)     v0 = 0.f;
            if (gm0 == gn + 1) v1 = 0.f;
            if (gm1 == gn)     v2 = 0.f;
            if (gm1 == gn + 1) v3 = 0.f;
            acc[i][j][0] = v0; acc[i][j][1] = v1;
            acc[i][j][2] = v2; acc[i][j][3] = v3;
            uint32_t q0 = (mwN[nl >> 5] >> (nl & 31)) & 1u;
            uint32_t q1 = (mwN[nl >> 5] >> ((nl + 1) & 31)) & 1u;
            float2 r0, r1;
            r0.x = q0 ? v0 : -FLT_MAX; r0.y = q1 ? v1 : -FLT_MAX;
            r1.x = q0 ? v2 : -FLT_MAX; r1.y = q1 ? v3 : -FLT_MAX;
            *(float2*)(C + (size_t)gm0 * NN + gn) = r0;
            *(float2*)(C + (size_t)gm1 * NN + gn) = r1;
        }
    }

    // mirror tile (column mask = M-side)
    if (ti != tj) {
        float* stg = (float*)smem;
        __syncthreads();
#pragma unroll
        for (int i = 0; i < 4; i++) {
            int ml0 = m0w + i * 16 + g;
            int ml1 = ml0 + 8;
            uint32_t q0 = (mwM[ml0 >> 5] >> (ml0 & 31)) & 1u;
            uint32_t q1 = (mwM[ml1 >> 5] >> (ml1 & 31)) & 1u;
#pragma unroll
            for (int j = 0; j < 4; j++) {
                int nl = n0w + j * 8 + 2 * tg;
                stg[(nl)     * TSTRIDE + ml0] = q0 ? acc[i][j][0] : -FLT_MAX;
                stg[(nl + 1) * TSTRIDE + ml0] = q0 ? acc[i][j][1] : -FLT_MAX;
                stg[(nl)     * TSTRIDE + ml1] = q1 ? acc[i][j][2] : -FLT_MAX;
                stg[(nl + 1) * TSTRIDE + ml1] = q1 ? acc[i][j][3] : -FLT_MAX;
            }
        }
        __syncthreads();
#pragma unroll
        for (int it = 0; it < 16; it++) {
            int idx = it * 256 + tid;
            int rr = idx >> 5;
            int c4 = idx & 31;
            float4 v = *(const float4*)&stg[rr * TSTRIDE + c4 * 4];
            *(float4*)(C + (size_t)(tileN + rr) * NN + tileM + c4 * 4) = v;
        }
    }
}

// ---------------- kernel 3: tournament top-20 (round-12 proven, scatter-only) ---
#define TPB3 128
__global__ __launch_bounds__(TPB3) void ktopk(float* __restrict__ out) {
    int b = blockIdx.y;
    int row = blockIdx.x;
    const float* simrow = g_sim + ((size_t)b * NN + row) * NN;
    float* orow = out + ((size_t)b * NN + row) * NN;

    __shared__ float sv[NN];
    __shared__ float cv[TPB3];
    __shared__ int   ci[TPB3];
    __shared__ float sel_v[KSEL];
    __shared__ int   sel_i[KSEL];
    __shared__ float fscale;

    int tid = threadIdx.x;
    int lane = tid & 31;

    // load + per-thread chunk max in one pass (mask already folded into sim)
    {
        float bv = -INFINITY; int bi = 0x7fffffff;
#pragma unroll
        for (int j = 0; j < 8; j++) {
            int i = tid * 4 + 512 * j;
            float4 v = *(const float4*)(simrow + i);
            *(float4*)(sv + i) = v;
            if (v.x > bv) { bv = v.x; bi = i; }
            if (v.y > bv) { bv = v.y; bi = i + 1; }
            if (v.z > bv) { bv = v.z; bi = i + 2; }
            if (v.w > bv) { bv = v.w; bi = i + 3; }
        }
        cv[tid] = bv; ci[tid] = bi;
    }
    __syncthreads();

    if (tid < 32) {
        for (int it = 0; it < KSEL; it++) {
            float bv = cv[lane]; int bi = ci[lane];
#pragma unroll
            for (int t2 = 1; t2 < 4; t2++) {
                float v = cv[lane + 32 * t2]; int i2 = ci[lane + 32 * t2];
                if (v > bv || (v == bv && i2 < bi)) { bv = v; bi = i2; }
            }
#pragma unroll
            for (int off = 16; off; off >>= 1) {
                float ov = __shfl_xor_sync(0xffffffffu, bv, off);
                int   oi = __shfl_xor_sync(0xffffffffu, bi, off);
                if (ov > bv || (ov == bv && oi < bi)) { bv = ov; bi = oi; }
            }
            if (lane == 0) {
                sel_v[it] = bv;
                sel_i[it] = bi;
                sv[bi] = -INFINITY;
            }
            __syncwarp();
            int c = (bi >> 2) & (TPB3 - 1);
            int idx = 4 * c + 512 * (lane >> 2) + (lane & 3);
            float nv = sv[idx]; int ni = idx;
#pragma unroll
            for (int off = 16; off; off >>= 1) {
                float ov = __shfl_xor_sync(0xffffffffu, nv, off);
                int   oi = __shfl_xor_sync(0xffffffffu, ni, off);
                if (ov > nv || (ov == nv && oi < ni)) { nv = ov; ni = oi; }
            }
            if (lane == 0) { cv[c] = nv; ci[c] = ni; }
            __syncwarp();
        }
        if (lane == 0) {
            float S = 0.f;
#pragma unroll
            for (int t2 = 0; t2 < KSEL; t2++) {
                float v = sel_v[t2];
                if (v < 0.f) v = 0.f;            // masked (-FLT_MAX) / negative -> 0
                if (sel_i[t2] == row) v = 0.f;   // diagonal
                sel_v[t2] = v;
                S += v;
            }
            float r1 = 1.f / fmaxf(S, EPSF);
            float S1 = S * r1;
            float r2 = 1.f / fmaxf(S1, EPSF);
            fscale = r1 * r2;
        }
    }
    __syncthreads();

    // out rows already zeroed by kgemm's fused zero blocks; scatter 20 values
    if (tid < KSEL) orow[sel_i[tid]] = sel_v[tid] * fscale;
}

// ---------------- launch ----------------
extern "C" void kernel_launch(void* const* d_in, const int* in_sizes, int n_in,
                              void* d_out, int out_size) {
    const float* hist = (const float*)d_in[0];
    const int* mask = (const int*)d_in[1];
    float* out = (float*)d_out;

    static int smem_set = 0;
    if (!smem_set) {
        cudaFuncSetAttribute(kgemm, cudaFuncAttributeMaxDynamicSharedMemorySize, SMEM_TOT);
        smem_set = 1;
    }

    kmask<<<BB, NN / 32>>>(mask);
    knorm<<<(BB * NN) / 4, 128>>>(hist, mask);

    dim3 g2(NUPPER + ZBLK, 1, BB);
    kgemm<<<g2, 256, SMEM_TOT>>>(out);

    dim3 g3(NN, BB);
    ktopk<<<g3, TPB3>>>(out);
}